// round 16
// baseline (speedup 1.0000x reference)
#include <cuda_runtime.h>

#define ROWS 38400
#define BIG  4915200

// ---------------- device scratch ----------------
__device__ float g_q[BIG];
__device__ float g_k[BIG];
__device__ float g_v[BIG];
__device__ float g_o[BIG];
__device__ float g_oa[BIG];
__device__ float g_dtw[BIG];
__device__ float g_ex[BIG];
__device__ float g_res[BIG];
__device__ float g_tmp[BIG];
__device__ float g_xp[786432];
__device__ float g_kp[786432];
__device__ float g_vp[786432];
__device__ float g_sen[51200];
__device__ float g_edge[51200];
__device__ float g_senx[51200];

// ---------------- mma / cp.async helpers ----------------
__device__ __forceinline__ void mma8(float* c, const unsigned* a, const unsigned* b) {
    asm volatile(
        "mma.sync.aligned.m16n8k8.row.col.f32.tf32.tf32.f32 "
        "{%0,%1,%2,%3}, {%4,%5,%6,%7}, {%8,%9}, {%0,%1,%2,%3};"
        : "+f"(c[0]), "+f"(c[1]), "+f"(c[2]), "+f"(c[3])
        : "r"(a[0]), "r"(a[1]), "r"(a[2]), "r"(a[3]), "r"(b[0]), "r"(b[1]));
}
__device__ __forceinline__ void cpa16(unsigned dst, const float* src, bool p) {
    int sz = p ? 16 : 0;
    asm volatile("cp.async.cg.shared.global [%0], [%1], 16, %2;"
                 :: "r"(dst), "l"(src), "r"(sz));
}
#define CP_COMMIT() asm volatile("cp.async.commit_group;")
#define CP_WAIT1()  asm volatile("cp.async.wait_group 1;")
#define CP_WAIT0()  asm volatile("cp.async.wait_group 0;")

// ---------------- batched tf32 GEMM (N=K=128) ----------------
struct GSet {
    const float* A[5];
    const float* W[5];
    const float* Bv[5];
    float*       C[5];
};
__global__ void __launch_bounds__(256) mma_gemm_b(GSet g, int M)
{
    extern __shared__ float smf[];
    float* As = smf;
    float* Bs = smf + 3 * 4608;
    const unsigned sA = (unsigned)__cvta_generic_to_shared(As);
    const unsigned sB = (unsigned)__cvta_generic_to_shared(Bs);
    const int y = blockIdx.y;
    const float* __restrict__ A = g.A[y];
    const float* __restrict__ W = g.W[y];
    const float* __restrict__ bias = g.Bv[y];
    float* __restrict__ C = g.C[y];
    const int tid = threadIdx.x;
    const int lane = tid & 31, w = tid >> 5;
    const int mw = (w >> 1) * 32, nw = (w & 1) * 64;
    const int rowBlk = blockIdx.x * 128;
    const int gp = lane >> 2, tg = lane & 3;

    float acc[2][8][4];
#pragma unroll
    for (int mt = 0; mt < 2; mt++)
#pragma unroll
        for (int nt = 0; nt < 8; nt++)
#pragma unroll
            for (int i = 0; i < 4; i++) acc[mt][nt][i] = 0.f;

    auto issue = [&](int t) {
        if (t < 4) {
            int s = t % 3, k0 = t * 32;
#pragma unroll
            for (int i = 0; i < 4; i++) {
                int idx = tid + i * 256;
                int r = idx >> 3, kq = idx & 7;
                int row = rowBlk + r;
                bool p = row < M;
                int rc = p ? row : (M - 1);
                cpa16(sA + (s * 4608 + r * 36 + kq * 4) * 4,
                      A + (long long)rc * 128 + k0 + kq * 4, p);
            }
#pragma unroll
            for (int i = 0; i < 4; i++) {
                int idx = tid + i * 256;
                int kk = idx >> 5, nq = idx & 31;
                cpa16(sB + (s * 4352 + kk * 136 + nq * 4) * 4,
                      W + (long long)(k0 + kk) * 128 + nq * 4, true);
            }
        }
        CP_COMMIT();
    };

    issue(0); issue(1);
    for (int t = 0; t < 4; t++) {
        CP_WAIT1();
        __syncthreads();
        const unsigned* Ad = (const unsigned*)(As + (t % 3) * 4608);
        const unsigned* Bd = (const unsigned*)(Bs + (t % 3) * 4352);
#pragma unroll
        for (int ks = 0; ks < 32; ks += 8) {
            unsigned a[2][4], b[8][2];
#pragma unroll
            for (int mt = 0; mt < 2; mt++) {
                int r = mw + mt * 16 + gp;
                a[mt][0] = Ad[r * 36 + ks + tg];
                a[mt][1] = Ad[(r + 8) * 36 + ks + tg];
                a[mt][2] = Ad[r * 36 + ks + tg + 4];
                a[mt][3] = Ad[(r + 8) * 36 + ks + tg + 4];
            }
#pragma unroll
            for (int nt = 0; nt < 8; nt++) {
                int n = nw + nt * 8 + gp;
                b[nt][0] = Bd[(ks + tg) * 136 + n];
                b[nt][1] = Bd[(ks + tg + 4) * 136 + n];
            }
#pragma unroll
            for (int mt = 0; mt < 2; mt++)
#pragma unroll
                for (int nt = 0; nt < 8; nt++)
                    mma8(acc[mt][nt], a[mt], b[nt]);
        }
        issue(t + 2);
    }
#pragma unroll
    for (int mt = 0; mt < 2; mt++) {
        int row = rowBlk + mw + mt * 16 + gp;
#pragma unroll
        for (int nt = 0; nt < 8; nt++) {
            int col = nw + nt * 8 + tg * 2;
            float b0 = bias[col], b1 = bias[col + 1];
            float* cp = acc[mt][nt];
            if (row < M)     *(float2*)&C[(long long)row * 128 + col]       = make_float2(cp[0] + b0, cp[1] + b1);
            if (row + 8 < M) *(float2*)&C[(long long)(row + 8) * 128 + col] = make_float2(cp[2] + b0, cp[3] + b1);
        }
    }
}

// ---------------- generic small GEMM (sen chain) ----------------
__global__ void __launch_bounds__(256) mma_gemm(
    const float* __restrict__ A, const float* __restrict__ W,
    const float* __restrict__ bias, float* __restrict__ C, int M)
{
    extern __shared__ float smf[];
    float* As = smf;
    float* Bs = smf + 3 * 4608;
    const unsigned sA = (unsigned)__cvta_generic_to_shared(As);
    const unsigned sB = (unsigned)__cvta_generic_to_shared(Bs);
    const int tid = threadIdx.x;
    const int lane = tid & 31, w = tid >> 5;
    const int mw = (w >> 1) * 32, nw = (w & 1) * 64;
    const int rowBlk = blockIdx.x * 128;
    const int gp = lane >> 2, tg = lane & 3;

    float acc[2][8][4];
#pragma unroll
    for (int mt = 0; mt < 2; mt++)
#pragma unroll
        for (int nt = 0; nt < 8; nt++)
#pragma unroll
            for (int i = 0; i < 4; i++) acc[mt][nt][i] = 0.f;

    auto issue = [&](int t) {
        if (t < 4) {
            int s = t % 3, k0 = t * 32;
#pragma unroll
            for (int i = 0; i < 4; i++) {
                int idx = tid + i * 256;
                int r = idx >> 3, kq = idx & 7;
                int row = rowBlk + r;
                bool p = row < M;
                int rc = p ? row : (M - 1);
                cpa16(sA + (s * 4608 + r * 36 + kq * 4) * 4,
                      A + (long long)rc * 128 + k0 + kq * 4, p);
            }
#pragma unroll
            for (int i = 0; i < 4; i++) {
                int idx = tid + i * 256;
                int kk = idx >> 5, nq = idx & 31;
                cpa16(sB + (s * 4352 + kk * 136 + nq * 4) * 4,
                      W + (long long)(k0 + kk) * 128 + nq * 4, true);
            }
        }
        CP_COMMIT();
    };

    issue(0); issue(1);
    for (int t = 0; t < 4; t++) {
        CP_WAIT1();
        __syncthreads();
        const unsigned* Ad = (const unsigned*)(As + (t % 3) * 4608);
        const unsigned* Bd = (const unsigned*)(Bs + (t % 3) * 4352);
#pragma unroll
        for (int ks = 0; ks < 32; ks += 8) {
            unsigned a[2][4], b[8][2];
#pragma unroll
            for (int mt = 0; mt < 2; mt++) {
                int r = mw + mt * 16 + gp;
                a[mt][0] = Ad[r * 36 + ks + tg];
                a[mt][1] = Ad[(r + 8) * 36 + ks + tg];
                a[mt][2] = Ad[r * 36 + ks + tg + 4];
                a[mt][3] = Ad[(r + 8) * 36 + ks + tg + 4];
            }
#pragma unroll
            for (int nt = 0; nt < 8; nt++) {
                int n = nw + nt * 8 + gp;
                b[nt][0] = Bd[(ks + tg) * 136 + n];
                b[nt][1] = Bd[(ks + tg + 4) * 136 + n];
            }
#pragma unroll
            for (int mt = 0; mt < 2; mt++)
#pragma unroll
                for (int nt = 0; nt < 8; nt++)
                    mma8(acc[mt][nt], a[mt], b[nt]);
        }
        issue(t + 2);
    }
#pragma unroll
    for (int mt = 0; mt < 2; mt++) {
        int row = rowBlk + mw + mt * 16 + gp;
#pragma unroll
        for (int nt = 0; nt < 8; nt++) {
            int col = nw + nt * 8 + tg * 2;
            float b0 = bias[col], b1 = bias[col + 1];
            float* cp = acc[mt][nt];
            if (row < M)     *(float2*)&C[(long long)row * 128 + col]       = make_float2(cp[0] + b0, cp[1] + b1);
            if (row + 8 < M) *(float2*)&C[(long long)(row + 8) * 128 + col] = make_float2(cp[2] + b0, cp[3] + b1);
        }
    }
}

// ---------------- fused FF: C = relu(A(*mulp) @ W1 + b1) @ W2 + b2, hidden in SMEM ----------------
#define FFF_A  0
#define FFF_W1 16896
#define FFF_H  26112
#define FFF_W2 34816
#define FFF_FLOATS 52224
__global__ void __launch_bounds__(256) ff_fused(
    const float* __restrict__ A, const float* __restrict__ W1,
    const float* __restrict__ b1v, const float* __restrict__ W2,
    const float* __restrict__ b2v, const float* __restrict__ mulp,
    float* __restrict__ C)
{
    extern __shared__ float smf[];
    float* As  = smf + FFF_A;
    float* W1s = smf + FFF_W1;
    float* Hs  = smf + FFF_H;
    float* W2s = smf + FFF_W2;
    const unsigned sW1 = (unsigned)__cvta_generic_to_shared(W1s);
    const unsigned sW2 = (unsigned)__cvta_generic_to_shared(W2s);
    const int tid = threadIdx.x;
    const int lane = tid & 31, w = tid >> 5;
    const int gp = lane >> 2, tg = lane & 3;
    const int mw1 = (w >> 1) * 32, nw1 = (w & 1) * 32;
    const int mw2 = (w >> 1) * 32, nw2 = (w & 1) * 64;
    const long long rowBlk = (long long)blockIdx.x * 128;

    for (int i = tid; i < 4096; i += 256) {
        int r = i >> 5, kq = i & 31;
        long long row = rowBlk + r;
        float4 av = *(const float4*)(A + row * 128 + kq * 4);
        if (mulp) {
            float4 mv = *(const float4*)(mulp + (row % 400) * 128 + kq * 4);
            av.x *= mv.x; av.y *= mv.y; av.z *= mv.z; av.w *= mv.w;
        }
        *(float4*)(As + r * 132 + kq * 4) = av;
    }

    auto loadW1 = [&](int c) {
#pragma unroll
        for (int i = 0; i < 8; i++) {
            int idx = tid + i * 256;
            int kk = idx >> 4, nq = idx & 15;
            cpa16(sW1 + (kk * 72 + nq * 4) * 4,
                  W1 + (long long)kk * 2048 + c * 64 + nq * 4, true);
        }
    };
    auto loadW2 = [&](int c, int buf) {
#pragma unroll
        for (int i = 0; i < 8; i++) {
            int idx = tid + i * 256;
            int kk = idx >> 5, nq = idx & 31;
            cpa16(sW2 + (buf * 8704 + kk * 136 + nq * 4) * 4,
                  W2 + (long long)(c * 64 + kk) * 128 + nq * 4, true);
        }
    };

    loadW1(0); loadW2(0, 0);
    CP_COMMIT();

    float acc[2][8][4];
#pragma unroll
    for (int mt = 0; mt < 2; mt++)
#pragma unroll
        for (int nt = 0; nt < 8; nt++)
#pragma unroll
            for (int i = 0; i < 4; i++) acc[mt][nt][i] = 0.f;

    CP_WAIT0();
    __syncthreads();

    const unsigned* Au = (const unsigned*)As;
    const unsigned* Hu = (const unsigned*)Hs;

    for (int c = 0; c < 32; c++) {
        float acc1[2][4][4];
#pragma unroll
        for (int mt = 0; mt < 2; mt++)
#pragma unroll
            for (int nt = 0; nt < 4; nt++)
#pragma unroll
                for (int i = 0; i < 4; i++) acc1[mt][nt][i] = 0.f;
        const unsigned* W1u = (const unsigned*)W1s;
#pragma unroll
        for (int ks = 0; ks < 128; ks += 8) {
            unsigned a[2][4], b[4][2];
#pragma unroll
            for (int mt = 0; mt < 2; mt++) {
                int r = mw1 + mt * 16 + gp;
                a[mt][0] = Au[r * 132 + ks + tg];
                a[mt][1] = Au[(r + 8) * 132 + ks + tg];
                a[mt][2] = Au[r * 132 + ks + tg + 4];
                a[mt][3] = Au[(r + 8) * 132 + ks + tg + 4];
            }
#pragma unroll
            for (int nt = 0; nt < 4; nt++) {
                int n = nw1 + nt * 8 + gp;
                b[nt][0] = W1u[(ks + tg) * 72 + n];
                b[nt][1] = W1u[(ks + tg + 4) * 72 + n];
            }
#pragma unroll
            for (int mt = 0; mt < 2; mt++)
#pragma unroll
                for (int nt = 0; nt < 4; nt++)
                    mma8(acc1[mt][nt], a[mt], b[nt]);
        }
        __syncthreads();
#pragma unroll
        for (int mt = 0; mt < 2; mt++) {
            int r = mw1 + mt * 16 + gp;
#pragma unroll
            for (int nt = 0; nt < 4; nt++) {
                int col = nw1 + nt * 8 + tg * 2;
                float g0 = b1v[c * 64 + col], g1 = b1v[c * 64 + col + 1];
                float* cp = acc1[mt][nt];
                *(float2*)&Hs[r * 68 + col] =
                    make_float2(fmaxf(cp[0] + g0, 0.f), fmaxf(cp[1] + g1, 0.f));
                *(float2*)&Hs[(r + 8) * 68 + col] =
                    make_float2(fmaxf(cp[2] + g0, 0.f), fmaxf(cp[3] + g1, 0.f));
            }
        }
        __syncthreads();
        if (c + 1 < 32) { loadW1(c + 1); loadW2(c + 1, (c + 1) & 1); }
        CP_COMMIT();
        const unsigned* W2u = (const unsigned*)(W2s + (c & 1) * 8704);
#pragma unroll
        for (int ks = 0; ks < 64; ks += 8) {
            unsigned a[2][4], b[8][2];
#pragma unroll
            for (int mt = 0; mt < 2; mt++) {
                int r = mw2 + mt * 16 + gp;
                a[mt][0] = Hu[r * 68 + ks + tg];
                a[mt][1] = Hu[(r + 8) * 68 + ks + tg];
                a[mt][2] = Hu[r * 68 + ks + tg + 4];
                a[mt][3] = Hu[(r + 8) * 68 + ks + tg + 4];
            }
#pragma unroll
            for (int nt = 0; nt < 8; nt++) {
                int n = nw2 + nt * 8 + gp;
                b[nt][0] = W2u[(ks + tg) * 136 + n];
                b[nt][1] = W2u[(ks + tg + 4) * 136 + n];
            }
#pragma unroll
            for (int mt = 0; mt < 2; mt++)
#pragma unroll
                for (int nt = 0; nt < 8; nt++)
                    mma8(acc[mt][nt], a[mt], b[nt]);
        }
        CP_WAIT0();
        __syncthreads();
    }
#pragma unroll
    for (int mt = 0; mt < 2; mt++) {
        long long row = rowBlk + mw2 + mt * 16 + gp;
#pragma unroll
        for (int nt = 0; nt < 8; nt++) {
            int col = nw2 + nt * 8 + tg * 2;
            float b0 = b2v[col], b1 = b2v[col + 1];
            float* cp = acc[mt][nt];
            *(float2*)&C[row * 128 + col]       = make_float2(cp[0] + b0, cp[1] + b1);
            *(float2*)&C[(row + 8) * 128 + col] = make_float2(cp[2] + b0, cp[3] + b1);
        }
    }
}

// ---------------- standalone tensor-core full attention (400 keys), 2 blocks/SM ----------------
#define ATT_KT 0
#define ATT_VT 6528
#define ATT_S  12992
#define ATT_QS 25920
#define ATT_PO 25920
#define ATT_LS 28096
#define ATT_TC_FLOATS 28128
__global__ void __launch_bounds__(256) attn_tc_kernel(
    const float* __restrict__ q, const float* __restrict__ k, const float* __restrict__ v,
    float* __restrict__ o)
{
    extern __shared__ float sm[];
    float* Kt = sm + ATT_KT;
    float* Vt = sm + ATT_VT;
    float* S  = sm + ATT_S;
    float* Qs = sm + ATT_QS;
    float* ls = sm + ATT_LS;
    float* Po = sm + ATT_PO;
    int bid = blockIdx.x, bt = bid >> 3, h = bid & 7;
    int tid = threadIdx.x, lane = tid & 31, w = tid >> 5;
    int gp = lane >> 2, tg = lane & 3;
    int base = bt * 400 * 128 + h * 16;

    for (int i = tid; i < 6400; i += 256) {
        int key = i >> 4, d = i & 15;
        Kt[d * 408 + key] = k[base + key * 128 + d];
        Vt[d * 404 + key] = v[base + key * 128 + d];
    }
    __syncthreads();

    const unsigned* Ku = (const unsigned*)Kt;
    const unsigned* Vu = (const unsigned*)Vt;
    const unsigned* Qu = (const unsigned*)Qs;
    const unsigned* Pu = (const unsigned*)S;

    for (int qt = 0; qt < 400; qt += 32) {
        for (int i = tid; i < 512; i += 256) {
            int r = i >> 4, d = i & 15;
            int qr = qt + r;
            Qs[r * 20 + d] = (qr < 400) ? q[base + qr * 128 + d] : 0.f;
        }
        __syncthreads();
        {
            unsigned af[2][2][4];
#pragma unroll
            for (int mt = 0; mt < 2; mt++)
#pragma unroll
                for (int ksi = 0; ksi < 2; ksi++) {
                    int r = mt * 16 + gp, ks = ksi * 8;
                    af[mt][ksi][0] = Qu[r * 20 + ks + tg];
                    af[mt][ksi][1] = Qu[(r + 8) * 20 + ks + tg];
                    af[mt][ksi][2] = Qu[r * 20 + ks + tg + 4];
                    af[mt][ksi][3] = Qu[(r + 8) * 20 + ks + tg + 4];
                }
            for (int nt = w; nt < 50; nt += 8) {
                float c0[4] = {0.f, 0.f, 0.f, 0.f};
                float c1[4] = {0.f, 0.f, 0.f, 0.f};
#pragma unroll
                for (int ksi = 0; ksi < 2; ksi++) {
                    int ks = ksi * 8;
                    unsigned b[2];
                    b[0] = Ku[(ks + tg) * 408 + nt * 8 + gp];
                    b[1] = Ku[(ks + tg + 4) * 408 + nt * 8 + gp];
                    mma8(c0, af[0][ksi], b);
                    mma8(c1, af[1][ksi], b);
                }
                int cc = nt * 8 + tg * 2;
                S[gp * 404 + cc]            = c0[0] * 0.25f;
                S[gp * 404 + cc + 1]        = c0[1] * 0.25f;
                S[(gp + 8) * 404 + cc]      = c0[2] * 0.25f;
                S[(gp + 8) * 404 + cc + 1]  = c0[3] * 0.25f;
                S[(gp + 16) * 404 + cc]     = c1[0] * 0.25f;
                S[(gp + 16) * 404 + cc + 1] = c1[1] * 0.25f;
                S[(gp + 24) * 404 + cc]     = c1[2] * 0.25f;
                S[(gp + 24) * 404 + cc + 1] = c1[3] * 0.25f;
            }
        }
        __syncthreads();
        for (int rr = 0; rr < 4; rr++) {
            int row = w * 4 + rr;
            float sc[13];
            float m = -3.4e38f;
#pragma unroll
            for (int j = 0; j < 13; j++) {
                int kk = lane + j * 32;
                float s_ = (kk < 400) ? S[row * 404 + kk] : -3.4e38f;
                sc[j] = s_; m = fmaxf(m, s_);
            }
#pragma unroll
            for (int off = 16; off; off >>= 1) m = fmaxf(m, __shfl_xor_sync(0xffffffffu, m, off));
            float l = 0.f;
#pragma unroll
            for (int j = 0; j < 13; j++) {
                int kk = lane + j * 32;
                if (kk < 400) {
                    float p_ = __expf(sc[j] - m);
                    S[row * 404 + kk] = p_;
                    l += p_;
                }
            }
#pragma unroll
            for (int off = 16; off; off >>= 1) l += __shfl_xor_sync(0xffffffffu, l, off);
            if (lane == 0) ls[row] = 1.f / l;
        }
        __syncthreads();
        {
            int mt = w & 1, nt = (w >> 1) & 1, kh = w >> 2;
            float c[4] = {0.f, 0.f, 0.f, 0.f};
            int kbase = kh * 200;
#pragma unroll 5
            for (int i = 0; i < 25; i++) {
                int k0 = kbase + i * 8;
                unsigned a[4], b[2];
                a[0] = Pu[(mt * 16 + gp) * 404 + k0 + tg];
                a[1] = Pu[(mt * 16 + gp + 8) * 404 + k0 + tg];
                a[2] = Pu[(mt * 16 + gp) * 404 + k0 + tg + 4];
                a[3] = Pu[(mt * 16 + gp + 8) * 404 + k0 + tg + 4];
                b[0] = Vu[(nt * 8 + gp) * 404 + k0 + tg];
                b[1] = Vu[(nt * 8 + gp) * 404 + k0 + tg + 4];
                mma8(c, a, b);
            }
            int r0 = mt * 16 + gp, d0 = nt * 8 + tg * 2;
            if (kh == 1) {
                Po[r0 * 68 + d0]           = c[0];
                Po[r0 * 68 + d0 + 1]       = c[1];
                Po[(r0 + 8) * 68 + d0]     = c[2];
                Po[(r0 + 8) * 68 + d0 + 1] = c[3];
            }
            __syncthreads();
            if (kh == 0) {
                float s0 = ls[r0], s1 = ls[r0 + 8];
                int qr0 = qt + r0, qr1 = qt + r0 + 8;
                if (qr0 < 400) {
                    o[base + qr0 * 128 + d0]     = (c[0] + Po[r0 * 68 + d0]) * s0;
                    o[base + qr0 * 128 + d0 + 1] = (c[1] + Po[r0 * 68 + d0 + 1]) * s0;
                }
                if (qr1 < 400) {
                    o[base + qr1 * 128 + d0]     = (c[2] + Po[(r0 + 8) * 68 + d0]) * s1;
                    o[base + qr1 * 128 + d0 + 1] = (c[3] + Po[(r0 + 8) * 68 + d0 + 1]) * s1;
                }
            }
        }
        __syncthreads();
    }
}

// ---------------- small-SMEM merged kernel: pooled attn (0-767) | gea node (768-1727) ----------------
__global__ void __launch_bounds__(256) small_both(
    const float* __restrict__ qa, const float* __restrict__ kp, const float* __restrict__ vp,
    const float* __restrict__ pos, float* __restrict__ oa,
    const float* __restrict__ gin, const float* __restrict__ gw, const float* __restrict__ gb,
    float* __restrict__ gout)
{
    __shared__ float sm[2624];   // 16*65 + 16*65 + 8*64 = 2624 floats (10.5 KB)
    int tid = threadIdx.x, lane = tid & 31, w = tid >> 5;

    if (blockIdx.x < 768) {
        float* Ks = sm;
        float* Vs = sm + 1040;
        float* pball = sm + 2080;
        int bid = blockIdx.x;
        int bt = bid >> 3, h = bid & 7;
        int kbase = bt * 64 * 128 + h * 16;
        int qbase = bt * 400 * 128 + h * 16;
        for (int i = tid; i < 1024; i += 256) {
            int kk = i >> 4, d = i & 15;
            Ks[d * 65 + kk] = kp[kbase + kk * 128 + d];
            Vs[d * 65 + kk] = vp[kbase + kk * 128 + d];
        }
        __syncthreads();
        float* pb = pball + w * 64;
        for (int qi = w; qi < 400; qi += 8) {
            float qd[16];
#pragma unroll
            for (int d = 0; d < 16; d++) qd[d] = qa[qbase + qi * 128 + d];
            float sc[2];
            float m = -3.4e38f;
#pragma unroll
            for (int j = 0; j < 2; j++) {
                int kk = lane + 32 * j;
                float s = 0.f;
#pragma unroll
                for (int d = 0; d < 16; d++) s += qd[d] * Ks[d * 65 + kk];
                s = s * 0.25f + pos[qi * 64 + kk];
                sc[j] = s; m = fmaxf(m, s);
            }
#pragma unroll
            for (int off = 16; off; off >>= 1) m = fmaxf(m, __shfl_xor_sync(0xffffffffu, m, off));
            float lsum = 0.f;
#pragma unroll
            for (int j = 0; j < 2; j++) { float p = __expf(sc[j] - m); sc[j] = p; lsum += p; }
#pragma unroll
            for (int off = 16; off; off >>= 1) lsum += __shfl_xor_sync(0xffffffffu, lsum, off);
            pb[lane] = sc[0]; pb[lane + 32] = sc[1];
            __syncwarp();
            int d = lane & 15, half = lane >> 4;
            float acc = 0.f;
#pragma unroll
            for (int i = 0; i < 32; ++i) { int c = 2 * i + half; acc += pb[c] * Vs[d * 65 + c]; }
            acc += __shfl_xor_sync(0xffffffffu, acc, 16);
            if (lane < 16) oa[qbase + qi * 128 + d] = acc / lsum;
            __syncwarp();
        }
    } else {
        // GEANet node: warp-per-row, 5 rows/warp
        int u = lane & 15, hh = lane >> 4;
        float w0c[16], w1c[16];
#pragma unroll
        for (int kk = 0; kk < 16; kk++) {
            w0c[kk] = gw[kk * 16 + u];
            w1c[kk] = gw[256 + kk * 16 + u];
        }
        float b0 = gb[u], b1 = gb[16 + u];
        int rowBase = ((blockIdx.x - 768) * 8 + w) * 5;
#pragma unroll
        for (int rr = 0; rr < 5; rr++) {
            int id = rowBase + rr;
            float xr[4];
#pragma unroll
            for (int j = 0; j < 4; j++)
                xr[j] = gin[(long long)id * 128 + (hh * 4 + j) * 16 + u];
            float a[4] = {b0, b0, b0, b0};
#pragma unroll
            for (int kk = 0; kk < 16; kk++) {
                int src = (hh << 4) | kk;
                float x0 = __shfl_sync(0xffffffffu, xr[0], src);
                float x1 = __shfl_sync(0xffffffffu, xr[1], src);
                float x2 = __shfl_sync(0xffffffffu, xr[2], src);
                float x3 = __shfl_sync(0xffffffffu, xr[3], src);
                a[0] += x0 * w0c[kk]; a[1] += x1 * w0c[kk];
                a[2] += x2 * w0c[kk]; a[3] += x3 * w0c[kk];
            }
            float mx = fmaxf(fmaxf(a[0], a[1]), fmaxf(a[2], a[3]));
            mx = fmaxf(mx, __shfl_xor_sync(0xffffffffu, mx, 16));
            float e0 = __expf(a[0] - mx), e1 = __expf(a[1] - mx);
            float e2 = __expf(a[2] - mx), e3 = __expf(a[3] - mx);
            float den = e0 + e1 + e2 + e3;
            den += __shfl_xor_sync(0xffffffffu, den, 16);
            float vv[4] = {e0 / den, e1 / den, e2 / den, e3 / den};
            float rs[4] = {vv[0], vv[1], vv[2], vv[3]};
#pragma unroll
            for (int msk = 1; msk < 16; msk <<= 1) {
                rs[0] += __shfl_xor_sync(0xffffffffu, rs[0], msk);
                rs[1] += __shfl_xor_sync(0xffffffffu, rs[1], msk);
                rs[2] += __shfl_xor_sync(0xffffffffu, rs[2], msk);
                rs[3] += __shfl_xor_sync(0xffffffffu, rs[3], msk);
            }
            float dn[4] = {vv[0] / rs[0], vv[1] / rs[1], vv[2] / rs[2], vv[3] / rs[3]};
            float o4[4] = {b1, b1, b1, b1};
#pragma unroll
            for (int kk = 0; kk < 16; kk++) {
                int src = (hh << 4) | kk;
                float x0 = __shfl_sync(0xffffffffu, dn[0], src);
                float x1 = __shfl_sync(0xffffffffu, dn[1], src);
                float x2 = __shfl_sync(0xffffffffu, dn[2], src);
                float x3 = __shfl_sync(0xffffffffu, dn[3], src);
                o4[0] += x0 * w1c[kk]; o4[1] += x1 * w1c[kk];
                o4[2] += x2 * w1c[kk]; o4[3] += x3 * w1c[kk];
            }
            int bI = id / 4800, r2 = id % 4800, t = r2 / 400, n = r2 % 400;
            long long ob = ((long long)(bI * 400 + n) * 12 + t) * 128;
#pragma unroll
            for (int j = 0; j < 4; j++) gout[ob + (hh * 4 + j) * 16 + u] = o4[j];
        }
    }
}

// ---------------- warp-per-row GEANet edge (standalone) ----------------
__global__ void __launch_bounds__(256) gea_edge(
    const float* __restrict__ in, const float* __restrict__ w, const float* __restrict__ bb,
    float* __restrict__ outp, float* __restrict__ outp2)
{
    int lane = threadIdx.x & 31, wid = threadIdx.x >> 5;
    int u = lane & 15, hh = lane >> 4;
    float w0c[16], w1c[16];
#pragma unroll
    for (int kk = 0; kk < 16; kk++) {
        w0c[kk] = w[kk * 16 + u];
        w1c[kk] = w[256 + kk * 16 + u];
    }
    float b0 = bb[u], b1 = bb[16 + u];
    int id = blockIdx.x * 8 + wid;
    if (id >= 400) return;
    float xr[4];
#pragma unroll
    for (int j = 0; j < 4; j++)
        xr[j] = in[(long long)id * 128 + u * 8 + (hh * 4 + j)];
    float a[4] = {b0, b0, b0, b0};
#pragma unroll
    for (int kk = 0; kk < 16; kk++) {
        int src = (hh << 4) | kk;
        float x0 = __shfl_sync(0xffffffffu, xr[0], src);
        float x1 = __shfl_sync(0xffffffffu, xr[1], src);
        float x2 = __shfl_sync(0xffffffffu, xr[2], src);
        float x3 = __shfl_sync(0xffffffffu, xr[3], src);
        a[0] += x0 * w0c[kk]; a[1] += x1 * w0c[kk];
        a[2] += x2 * w0c[kk]; a[3] += x3 * w0c[kk];
    }
    float mx = fmaxf(fmaxf(a[0], a[1]), fmaxf(a[2], a[3]));
    mx = fmaxf(mx, __shfl_xor_sync(0xffffffffu, mx, 16));
    float e0 = __expf(a[0] - mx), e1 = __expf(a[1] - mx);
    float e2 = __expf(a[2] - mx), e3 = __expf(a[3] - mx);
    float den = e0 + e1 + e2 + e3;
    den += __shfl_xor_sync(0xffffffffu, den, 16);
    float vv[4] = {e0 / den, e1 / den, e2 / den, e3 / den};
    float rs[4] = {vv[0], vv[1], vv[2], vv[3]};
#pragma unroll
    for (int msk = 1; msk < 16; msk <<= 1) {
        rs[0] += __shfl_xor_sync(0xffffffffu, rs[0], msk);
        rs[1] += __shfl_xor_sync(0xffffffffu, rs[1], msk);
        rs[2] += __shfl_xor_sync(0xffffffffu, rs[2], msk);
        rs[3] += __shfl_xor_sync(0xffffffffu, rs[3], msk);
    }
    float dn[4] = {vv[0] / rs[0], vv[1] / rs[1], vv[2] / rs[2], vv[3] / rs[3]};
    float o4[4] = {b1, b1, b1, b1};
#pragma unroll
    for (int kk = 0; kk < 16; kk++) {
        int src = (hh << 4) | kk;
        float x0 = __shfl_sync(0xffffffffu, dn[0], src);
        float x1 = __shfl_sync(0xffffffffu, dn[1], src);
        float x2 = __shfl_sync(0xffffffffu, dn[2], src);
        float x3 = __shfl_sync(0xffffffffu, dn[3], src);
        o4[0] += x0 * w1c[kk]; o4[1] += x1 * w1c[kk];
        o4[2] += x2 * w1c[kk]; o4[3] += x3 * w1c[kk];
    }
    long long ob = (long long)id * 128;
#pragma unroll
    for (int j = 0; j < 4; j++) {
        int dloc = (hh * 4 + j) * 16 + u;
        outp[ob + dloc] = o4[j];
        if (outp2) outp2[ob + dloc] = o4[j];
    }
}

// ---------------- warp-per-row LayerNorm ----------------
__global__ void __launch_bounds__(128) ln4_kernel(
    const float* __restrict__ a, const float* __restrict__ b,
    const float* __restrict__ c, const float* __restrict__ d,
    const float* __restrict__ gamma, const float* __restrict__ beta,
    float* __restrict__ out, const float* __restrict__ addp)
{
    int lane = threadIdx.x & 31, wid = threadIdx.x >> 5;
    long long row = (long long)blockIdx.x * 4 + wid;
    long long base = row * 128 + lane * 4;
    float4 v = *(const float4*)(a + base);
    if (b) { float4 t = *(const float4*)(b + base); v.x += t.x; v.y += t.y; v.z += t.z; v.w += t.w; }
    if (c) { float4 t = *(const float4*)(c + base); v.x += t.x; v.y += t.y; v.z += t.z; v.w += t.w; }
    if (d) { float4 t = *(const float4*)(d + base); v.x += t.x; v.y += t.y; v.z += t.z; v.w += t.w; }
    float s = v.x + v.y + v.z + v.w;
    float ss = v.x * v.x + v.y * v.y + v.z * v.z + v.w * v.w;
#pragma unroll
    for (int off = 16; off; off >>= 1) {
        s  += __shfl_xor_sync(0xffffffffu, s,  off);
        ss += __shfl_xor_sync(0xffffffffu, ss, off);
    }
    float m = s * (1.f / 128.f);
    float var = ss * (1.f / 128.f) - m * m;
    float inv = rsqrtf(var + 1e-5f);
    float4 g  = *(const float4*)(gamma + lane * 4);
    float4 be = *(const float4*)(beta + lane * 4);
    float4 r;
    r.x = (v.x - m) * inv * g.x + be.x;
    r.y = (v.y - m) * inv * g.y + be.y;
    r.z = (v.z - m) * inv * g.z + be.z;
    r.w = (v.w - m) * inv * g.w + be.w;
    if (addp) {
        float4 t = *(const float4*)(addp + base);
        r.x += t.x; r.y += t.y; r.z += t.z; r.w += t.w;
    }
    *(float4*)(out + base) = r;
}

// ---------------- adaptive avg pool ----------------
__global__ void __launch_bounds__(128) pool_kernel(const float* __restrict__ x, float* __restrict__ xp)
{
    int bid = blockIdx.x;
    int bt = bid >> 6, c = bid & 63;
    int s = (c * 400) >> 6;
    int e = ((c + 1) * 400 + 63) >> 6;
    float sum = 0.f;
    for (int n = s; n < e; ++n) sum += x[(bt * 400 + n) * 128 + threadIdx.x];
    xp[bid * 128 + threadIdx.x] = sum / (float)(e - s);
}

// ---------------- host ----------------
static float* sym(const void* s) { void* p = nullptr; cudaGetSymbolAddress(&p, s); return (float*)p; }

extern "C" void kernel_launch(void* const* d_in, const int* in_sizes, int n_in,
                              void* d_out, int out_size)
{
    const float* x      = (const float*)d_in[0];
    const float* semb   = (const float*)d_in[1];
    const float* dqkv_w = (const float*)d_in[2];
    const float* dqkv_b = (const float*)d_in[3];
    const float* dout_w = (const float*)d_in[4];
    const float* dout_b = (const float*)d_in[5];
    const float* aqkv_w = (const float*)d_in[6];
    const float* aqkv_b = (const float*)d_in[7];
    const float* aout_w = (const float*)d_in[8];
    const float* aout_b = (const float*)d_in[9];
    const float* adp_pos= (const float*)d_in[10];
    const float* gsh_w  = (const float*)d_in[11];
    const float* gsh_b  = (const float*)d_in[12];
    const float* gnode_w= (const float*)d_in[13];
    const float* gnode_b= (const float*)d_in[14];
    const float* gedge_w= (const float*)d_in[15];
    const float* gedge_b= (const float*)d_in[16];
    const float* sp_w   = (const float*)d_in[17];
    const float* sp_b   = (const float*)d_in[18];
    const float* f1w1   = (const float*)d_in[19];
    const float* f1b1   = (const float*)d_in[20];
    const float* f1w2   = (const float*)d_in[21];
    const float* f1b2   = (const float*)d_in[22];
    const float* f2w1   = (const float*)d_in[23];
    const float* f2b1   = (const float*)d_in[24];
    const float* f2w2   = (const float*)d_in[25];
    const float* f2b2   = (const float*)d_in[26];
    const float* lns    = (const float*)d_in[27];
    const float* lnb    = (const float*)d_in[28];
    float* out = (float*)d_out;

    float *q = sym(g_q), *k = sym(g_k), *v = sym(g_v), *o = sym(g_o), *oa = sym(g_oa);
    float *dtw = sym(g_dtw), *ex = sym(g_ex), *res = sym(g_res), *tmp = sym(g_tmp);
    float *xp = sym(g_xp), *kp = sym(g_kp), *vp = sym(g_vp);
    float *sen = sym(g_sen), *edge = sym(g_edge), *senx = sym(g_senx);

    const int GEMM_SMEM = 3 * (4608 + 4352) * 4;   // 107520 B
    const int ATT_SMEM  = ATT_TC_FLOATS * 4;       // 112512 B -> 2 blocks/SM
    const int FFF_SMEM  = FFF_FLOATS * 4;          // 208896 B
    cudaFuncSetAttribute(mma_gemm,   cudaFuncAttributeMaxDynamicSharedMemorySize, GEMM_SMEM);
    cudaFuncSetAttribute(mma_gemm_b, cudaFuncAttributeMaxDynamicSharedMemorySize, GEMM_SMEM);
    cudaFuncSetAttribute(attn_tc_kernel, cudaFuncAttributeMaxDynamicSharedMemorySize, ATT_SMEM);
    cudaFuncSetAttribute(ff_fused, cudaFuncAttributeMaxDynamicSharedMemorySize, FFF_SMEM);

    // batch 1: five projections reading x
    GSet b1;
    b1.A[0] = x; b1.W[0] = dqkv_w;          b1.Bv[0] = dqkv_b;        b1.C[0] = q;
    b1.A[1] = x; b1.W[1] = dqkv_w + 16384;  b1.Bv[1] = dqkv_b + 128;  b1.C[1] = k;
    b1.A[2] = x; b1.W[2] = dqkv_w + 32768;  b1.Bv[2] = dqkv_b + 256;  b1.C[2] = v;
    b1.A[3] = x; b1.W[3] = aqkv_w;          b1.Bv[3] = aqkv_b;        b1.C[3] = tmp;
    b1.A[4] = x; b1.W[4] = gsh_w;           b1.Bv[4] = gsh_b;         b1.C[4] = res;
    mma_gemm_b<<<dim3(300, 5), 256, GEMM_SMEM>>>(b1, ROWS);

    pool_kernel<<<6144, 128>>>(x, xp);

    // batch 2: pooled K/V
    GSet b2;
    b2.A[0] = xp; b2.W[0] = aqkv_w + 16384; b2.Bv[0] = aqkv_b + 128; b2.C[0] = kp;
    b2.A[1] = xp; b2.W[1] = aqkv_w + 32768; b2.Bv[1] = aqkv_b + 256; b2.C[1] = vp;
    b2.A[2] = xp; b2.W[2] = b2.W[0];        b2.Bv[2] = b2.Bv[0];     b2.C[2] = kp;
    b2.A[3] = xp; b2.W[3] = b2.W[0];        b2.Bv[3] = b2.Bv[0];     b2.C[3] = kp;
    b2.A[4] = xp; b2.W[4] = b2.W[0];        b2.Bv[4] = b2.Bv[0];     b2.C[4] = kp;
    mma_gemm_b<<<dim3(48, 2), 256, GEMM_SMEM>>>(b2, 6144);

    // small-SMEM merged: pooled attn + gea node (independent of full attn)
    small_both<<<1728, 256>>>(tmp, kp, vp, adp_pos, oa, res, gnode_w, gnode_b, ex);

    // full tensor-core attention (2 blocks/SM)
    attn_tc_kernel<<<768, 256, ATT_SMEM>>>(q, k, v, o);

    // batch 3: output projections
    GSet b3;
    b3.A[0] = o;  b3.W[0] = dout_w; b3.Bv[0] = dout_b; b3.C[0] = dtw;
    b3.A[1] = oa; b3.W[1] = aout_w; b3.Bv[1] = aout_b; b3.C[1] = k;    // oa-proj -> k
    b3.A[2] = o;  b3.W[2] = b3.W[0]; b3.Bv[2] = b3.Bv[0]; b3.C[2] = dtw;
    b3.A[3] = o;  b3.W[3] = b3.W[0]; b3.Bv[3] = b3.Bv[0]; b3.C[3] = dtw;
    b3.A[4] = o;  b3.W[4] = b3.W[0]; b3.Bv[4] = b3.Bv[0]; b3.C[4] = dtw;
    mma_gemm_b<<<dim3(300, 2), 256, GEMM_SMEM>>>(b3, ROWS);

    // sen + GEANet edge (dual-writes senx and output tail)
    mma_gemm<<<4, 256, GEMM_SMEM>>>(semb, sp_w, sp_b, sen, 400);
    ln4_kernel<<<100, 128>>>(sen, nullptr, nullptr, nullptr, lns + 3 * 128, lnb + 3 * 128, sen, nullptr);
    mma_gemm<<<4, 256, GEMM_SMEM>>>(sen, gsh_w, gsh_b, edge, 400);
    gea_edge<<<50, 256>>>(edge, gedge_w, gedge_b, senx,
                          (out_size >= BIG + 51200) ? (out + BIG) : nullptr);

    // out = LN(x + dtw + oa_proj + extra)
    ln4_kernel<<<9600, 128>>>(x, dtw, k, ex, lns, lnb, res, nullptr);

    // out_attn = LN(FF1(out) + out)
    ff_fused<<<300, 256, FFF_SMEM>>>(res, f1w1, f1b1, f1w2, f1b2, nullptr, tmp);
    ln4_kernel<<<9600, 128>>>(tmp, res, nullptr, nullptr, lns + 128, lnb + 128, dtw, nullptr);

    // sp = LN(FF2(out_attn * sen_extra)); final out = out_attn + sp fused into LN
    ff_fused<<<300, 256, FFF_SMEM>>>(dtw, f2w1, f2b1, f2w2, f2b2, senx, tmp);
    ln4_kernel<<<9600, 128>>>(tmp, nullptr, nullptr, nullptr, lns + 256, lnb + 256, out, dtw);
}